// round 5
// baseline (speedup 1.0000x reference)
#include <cuda_runtime.h>
#include <cuda_bf16.h>
#include <math.h>
#include <stdint.h>

#define Mq 1024
#define Nn 4096
#define Dd 128
#define Pp 3072
#define Hh 32
#define NKEYS 4096
typedef __nv_bfloat16 bf16;

// ---------------- scratch ----------------
__device__ bf16 g_Xh[(size_t)Mq * Nn],       g_Xl[(size_t)Mq * Nn];
__device__ bf16 g_Wh[(size_t)3 * Nn * Nn],   g_Wl[(size_t)3 * Nn * Nn];      // W^T
__device__ bf16 g_Qh[(size_t)Hh * Mq * Dd],  g_Ql[(size_t)Hh * Mq * Dd];
__device__ bf16 g_Kh[(size_t)Hh * NKEYS * Dd], g_Kl[(size_t)Hh * NKEYS * Dd];
__device__ bf16 g_Vth[(size_t)Hh * Dd * NKEYS], g_Vtl[(size_t)Hh * Dd * NKEYS]; // V^T

// ---------------- helpers ----------------
static __device__ __forceinline__ uint32_t smem_u32(const void* p) {
    uint32_t a;
    asm("{ .reg .u64 t; cvta.to.shared.u64 t, %1; cvt.u32.u64 %0, t; }" : "=r"(a) : "l"(p));
    return a;
}
static __device__ __forceinline__ void cp_async16(uint32_t dst, const void* src) {
    asm volatile("cp.async.cg.shared.global [%0], [%1], 16;" :: "r"(dst), "l"(src));
}
#define CP_COMMIT() asm volatile("cp.async.commit_group;" ::: "memory")
#define CP_WAIT(n)  asm volatile("cp.async.wait_group %0;" :: "n"(n) : "memory")

static __device__ __forceinline__ void ldsm_x4(uint32_t& r0, uint32_t& r1, uint32_t& r2, uint32_t& r3,
                                               uint32_t addr) {
    asm volatile("ldmatrix.sync.aligned.m8n8.x4.shared.b16 {%0,%1,%2,%3}, [%4];"
                 : "=r"(r0), "=r"(r1), "=r"(r2), "=r"(r3) : "r"(addr));
}
static __device__ __forceinline__ void mma_bf16(float* c, const uint32_t* a, const uint32_t* b) {
    asm volatile(
        "mma.sync.aligned.m16n8k16.row.col.f32.bf16.bf16.f32 "
        "{%0,%1,%2,%3}, {%4,%5,%6,%7}, {%8,%9}, {%0,%1,%2,%3};"
        : "+f"(c[0]), "+f"(c[1]), "+f"(c[2]), "+f"(c[3])
        : "r"(a[0]), "r"(a[1]), "r"(a[2]), "r"(a[3]), "r"(b[0]), "r"(b[1]));
}
static __device__ __forceinline__ void split_bf16(float v, bf16& h, bf16& l) {
    h = __float2bfloat16(v);
    l = __float2bfloat16(v - __bfloat162float(h));
}

#define SMEM_PROJ (1024 + 2 * 4 * 16384)          // rbuf + 2 stages * 4 planes
#define SMEM_ATT  (1024 + 3 * 4 * 16384)          // rbuf + Q + K/P + V regions

// ---------------- projection GEMM (bf16x2 split, HMMA, fragment reuse) ----------------
// C[m][n] = sum_k A[m][k]*B[n][k]; 128x128 tile; MODE 0=Q(RMS), 1=K(RMS,+P), 2=V(transpose)
template <int MODE>
__global__ __launch_bounds__(256, 1) void proj_kernel(
    const bf16* __restrict__ Ah, const bf16* __restrict__ Al, int lda,
    const bf16* __restrict__ Bh, const bf16* __restrict__ Bl, int ldb, int kdim)
{
    extern __shared__ char smem[];
    float* rbuf = (float*)smem;
    const uint32_t sb = smem_u32(smem);
    const int tid = threadIdx.x;
    const int wid = tid >> 5, l = tid & 31;
    const int wm = wid >> 1, wn = wid & 1;
    const int bn = blockIdx.x * 128, bm = blockIdx.y * 128;

    float acc[2][8][4];
#pragma unroll
    for (int t = 0; t < 2; t++)
#pragma unroll
        for (int nb = 0; nb < 8; nb++)
#pragma unroll
            for (int i = 0; i < 4; i++) acc[t][nb][i] = 0.f;

    const int nch = kdim >> 6;

    auto load_chunk = [&](int c) {
        const int st = c & 1;
        const int k0 = c << 6;
#pragma unroll
        for (int p = 0; p < 4; p++) {
            const bf16* src = (p == 0) ? Ah : (p == 1) ? Al : (p == 2) ? Bh : Bl;
            const int ld = (p < 2) ? lda : ldb;
            const int r0 = (p < 2) ? bm : bn;
            const uint32_t dstb = sb + 1024 + st * 65536 + p * 16384;
#pragma unroll
            for (int i = tid; i < 1024; i += 256) {
                const int row = i >> 3, cc = i & 7;
                const uint32_t off = (uint32_t)(row * 128 + cc * 16);
                cp_async16(dstb + (off ^ (uint32_t)((row & 7) << 4)),
                           src + (size_t)(r0 + row) * ld + k0 + cc * 8);
            }
        }
        CP_COMMIT();
    };

    load_chunk(0);
    if (nch > 1) load_chunk(1);

    for (int c = 0; c < nch; c++) {
        if (c + 1 < nch) { CP_WAIT(1); } else { CP_WAIT(0); }
        __syncthreads();
        const uint32_t sbase = sb + 1024 + (c & 1) * 65536;

#pragma unroll
        for (int kk = 0; kk < 4; kk++) {
            uint32_t aH[2][4], aL[2][4];
#pragma unroll
            for (int t = 0; t < 2; t++) {
                const int mrow = wm * 32 + t * 16 + (l & 7) + ((l >> 3) & 1) * 8;
                const int kb = kk * 32 + ((l >> 4) & 1) * 16;
                const uint32_t ao = (uint32_t)(mrow * 128) + (uint32_t)(kb ^ ((mrow & 7) << 4));
                ldsm_x4(aH[t][0], aH[t][1], aH[t][2], aH[t][3], sbase + 0 * 16384 + ao);
                ldsm_x4(aL[t][0], aL[t][1], aL[t][2], aL[t][3], sbase + 1 * 16384 + ao);
            }
            uint32_t bH[8][2], bL[8][2];
#pragma unroll
            for (int bt = 0; bt < 4; bt++) {
                const int nrow = wn * 64 + bt * 16 + (l & 7) + ((l >> 4) & 1) * 8;
                const int kb = kk * 32 + ((l >> 3) & 1) * 16;
                const uint32_t bo = (uint32_t)(nrow * 128) + (uint32_t)(kb ^ ((nrow & 7) << 4));
                ldsm_x4(bH[2 * bt][0], bH[2 * bt][1], bH[2 * bt + 1][0], bH[2 * bt + 1][1],
                        sbase + 2 * 16384 + bo);
                ldsm_x4(bL[2 * bt][0], bL[2 * bt][1], bL[2 * bt + 1][0], bL[2 * bt + 1][1],
                        sbase + 3 * 16384 + bo);
            }
#pragma unroll
            for (int t = 0; t < 2; t++)
#pragma unroll
                for (int nb = 0; nb < 8; nb++) {
                    mma_bf16(acc[t][nb], aH[t], bH[nb]);
                    mma_bf16(acc[t][nb], aH[t], bL[nb]);
                    mma_bf16(acc[t][nb], aL[t], bH[nb]);
                }
        }
        __syncthreads();
        if (c + 2 < nch) load_chunk(c + 2);
    }

    // epilogues: acc[t][nb][i] -> row = wm*32+t*16+(l>>2)+(i>>1)*8, col = wn*64+nb*8+(l&3)*2+(i&1)
    if (MODE == 0 || MODE == 1) {
        float ss[4] = {0.f, 0.f, 0.f, 0.f};
#pragma unroll
        for (int t = 0; t < 2; t++)
#pragma unroll
            for (int nb = 0; nb < 8; nb++)
#pragma unroll
                for (int i = 0; i < 4; i++) {
                    const float v = acc[t][nb][i];
                    ss[t * 2 + (i >> 1)] += v * v;
                }
#pragma unroll
        for (int s = 0; s < 4; s++) {
            ss[s] += __shfl_xor_sync(0xffffffffu, ss[s], 1);
            ss[s] += __shfl_xor_sync(0xffffffffu, ss[s], 2);
        }
        if ((l & 3) == 0) {
#pragma unroll
            for (int s = 0; s < 4; s++) {
                const int row = wm * 32 + (s >> 1) * 16 + (l >> 2) + (s & 1) * 8;
                rbuf[wn * 128 + row] = ss[s];
            }
        }
        __syncthreads();

        bf16* dh = (MODE == 0) ? g_Qh : g_Kh;
        bf16* dl = (MODE == 0) ? g_Ql : g_Kl;
#pragma unroll
        for (int t = 0; t < 2; t++)
#pragma unroll
            for (int rh = 0; rh < 2; rh++) {
                const int row = wm * 32 + t * 16 + (l >> 2) + rh * 8;
                const float sc = rsqrtf((rbuf[row] + rbuf[128 + row]) * (1.0f / 128.0f));
                const size_t rowbase = (MODE == 0)
                    ? ((size_t)blockIdx.x * Mq + bm + row) * 128
                    : ((size_t)blockIdx.x * NKEYS + Pp + bm + row) * 128;
#pragma unroll
                for (int nb = 0; nb < 8; nb++) {
                    const int col = wn * 64 + nb * 8 + (l & 3) * 2;
                    const float v0 = acc[t][nb][rh * 2 + 0] * sc;
                    const float v1 = acc[t][nb][rh * 2 + 1] * sc;
                    bf16 h0, l0, h1, l1;
                    split_bf16(v0, h0, l0);
                    split_bf16(v1, h1, l1);
                    __nv_bfloat162 ph; ph.x = h0; ph.y = h1;
                    __nv_bfloat162 pl; pl.x = l0; pl.y = l1;
                    *(__nv_bfloat162*)(dh + rowbase + col) = ph;
                    *(__nv_bfloat162*)(dl + rowbase + col) = pl;
                }
            }
    } else { // MODE 2: V transposed store
        const int head = blockIdx.x;
#pragma unroll
        for (int t = 0; t < 2; t++)
#pragma unroll
            for (int nb = 0; nb < 8; nb++)
#pragma unroll
                for (int i = 0; i < 4; i++) {
                    const int row = wm * 32 + t * 16 + (l >> 2) + (i >> 1) * 8;
                    const int col = wn * 64 + nb * 8 + (l & 3) * 2 + (i & 1);
                    bf16 h, lo;
                    split_bf16(acc[t][nb][i], h, lo);
                    const size_t idx = ((size_t)head * Dd + col) * NKEYS + Pp + bm + row;
                    g_Vth[idx] = h;
                    g_Vtl[idx] = lo;
                }
    }
}

// ---------------- fused flash attention ----------------
// grid (Mq/128, Hh); per CTA: Q tile resident; loop 32 key tiles:
// S = Q K^T (split MMA), exp in regs, P split -> smem (K region), out += P V^T (split MMA).
__global__ __launch_bounds__(256, 1) void attn_kernel(float* __restrict__ outp)
{
    extern __shared__ char smem[];
    float* rbuf = (float*)smem;
    const uint32_t sb = smem_u32(smem);
    const uint32_t Qb = sb + 1024;
    const uint32_t Kb = Qb + 65536;
    const uint32_t Vb = Kb + 65536;
    char* Kc = smem + 1024 + 65536;   // byte pointer to K/P region

    const int tid = threadIdx.x;
    const int wid = tid >> 5, l = tid & 31;
    const int wm = wid >> 1, wn = wid & 1;
    const int bm = blockIdx.x * 128;
    const int z = blockIdx.y;

    const bf16* Qhp = g_Qh + ((size_t)z * Mq + bm) * Dd;
    const bf16* Qlp = g_Ql + ((size_t)z * Mq + bm) * Dd;
    const bf16* Khp = g_Kh + (size_t)z * NKEYS * Dd;
    const bf16* Klp = g_Kl + (size_t)z * NKEYS * Dd;
    const bf16* Vhp = g_Vth + (size_t)z * Dd * NKEYS;
    const bf16* Vlp = g_Vtl + (size_t)z * Dd * NKEYS;

    // plane layout in each 64KB region: p = split*2 + chunk (chunk = 64-elem half of k-dim)
    auto load_region = [&](uint32_t dstb, const bf16* srcH, const bf16* srcL,
                           int ld, int row0, int col0) {
#pragma unroll
        for (int p = 0; p < 4; p++) {
            const bf16* src = (p < 2) ? srcH : srcL;
            const int k0 = col0 + (p & 1) * 64;
#pragma unroll
            for (int i = tid; i < 1024; i += 256) {
                const int row = i >> 3, cc = i & 7;
                const uint32_t off = (uint32_t)(row * 128 + cc * 16);
                cp_async16(dstb + p * 16384 + (off ^ (uint32_t)((row & 7) << 4)),
                           src + (size_t)(row0 + row) * ld + k0 + cc * 8);
            }
        }
    };

    // split-MMA over one 128-deep k dim: A region planes [abase], B region [bbase]
    auto do_mma = [&](uint32_t abase, uint32_t bbase, float acc[2][8][4]) {
#pragma unroll
        for (int c = 0; c < 2; c++) {
            const uint32_t aHb = abase + c * 16384, aLb = abase + (2 + c) * 16384;
            const uint32_t bHb = bbase + c * 16384, bLb = bbase + (2 + c) * 16384;
#pragma unroll
            for (int kk = 0; kk < 4; kk++) {
                uint32_t aH[2][4], aL[2][4];
#pragma unroll
                for (int t = 0; t < 2; t++) {
                    const int mrow = wm * 32 + t * 16 + (l & 7) + ((l >> 3) & 1) * 8;
                    const int kb = kk * 32 + ((l >> 4) & 1) * 16;
                    const uint32_t ao = (uint32_t)(mrow * 128) + (uint32_t)(kb ^ ((mrow & 7) << 4));
                    ldsm_x4(aH[t][0], aH[t][1], aH[t][2], aH[t][3], aHb + ao);
                    ldsm_x4(aL[t][0], aL[t][1], aL[t][2], aL[t][3], aLb + ao);
                }
                uint32_t bH[8][2], bL[8][2];
#pragma unroll
                for (int bt = 0; bt < 4; bt++) {
                    const int nrow = wn * 64 + bt * 16 + (l & 7) + ((l >> 4) & 1) * 8;
                    const int kb = kk * 32 + ((l >> 3) & 1) * 16;
                    const uint32_t bo = (uint32_t)(nrow * 128) + (uint32_t)(kb ^ ((nrow & 7) << 4));
                    ldsm_x4(bH[2 * bt][0], bH[2 * bt][1], bH[2 * bt + 1][0], bH[2 * bt + 1][1], bHb + bo);
                    ldsm_x4(bL[2 * bt][0], bL[2 * bt][1], bL[2 * bt + 1][0], bL[2 * bt + 1][1], bLb + bo);
                }
#pragma unroll
                for (int t = 0; t < 2; t++)
#pragma unroll
                    for (int nb = 0; nb < 8; nb++) {
                        mma_bf16(acc[t][nb], aH[t], bH[nb]);
                        mma_bf16(acc[t][nb], aH[t], bL[nb]);
                        mma_bf16(acc[t][nb], aL[t], bH[nb]);
                    }
            }
        }
    };

    float accO[2][8][4];
#pragma unroll
    for (int t = 0; t < 2; t++)
#pragma unroll
        for (int nb = 0; nb < 8; nb++)
#pragma unroll
            for (int i = 0; i < 4; i++) accO[t][nb][i] = 0.f;
    float rs[4] = {0.f, 0.f, 0.f, 0.f};

    // prologue: Q tile + K tile 0 in one group
    load_region(Qb, Qhp, Qlp, Dd, 0, 0);
    load_region(Kb, Khp, Klp, Dd, 0, 0);
    CP_COMMIT();

    for (int it = 0; it < NKEYS / 128; it++) {
        const int bn = it * 128;
        // issue V_it (V buffer free since end of previous iter)
        load_region(Vb, Vhp, Vlp, NKEYS, 0, bn);
        CP_COMMIT();

        CP_WAIT(1);            // K_it (and Q on first iter) complete
        __syncthreads();

        float accS[2][8][4];
#pragma unroll
        for (int t = 0; t < 2; t++)
#pragma unroll
            for (int nb = 0; nb < 8; nb++)
#pragma unroll
                for (int i = 0; i < 4; i++) accS[t][nb][i] = 0.f;

        do_mma(Qb, Kb, accS);   // S = Q K^T
        __syncthreads();        // all warps done reading K region

        // exp + split + store P into K region; accumulate row sums
#pragma unroll
        for (int t = 0; t < 2; t++)
#pragma unroll
            for (int rh = 0; rh < 2; rh++) {
                const int row = wm * 32 + t * 16 + (l >> 2) + rh * 8;
#pragma unroll
                for (int nb = 0; nb < 8; nb++) {
                    const int col = wn * 64 + nb * 8 + (l & 3) * 2;
                    const float e0 = __expf(accS[t][nb][rh * 2 + 0]);
                    const float e1 = __expf(accS[t][nb][rh * 2 + 1]);
                    rs[t * 2 + rh] += e0 + e1;
                    bf16 h0, l0, h1, l1;
                    split_bf16(e0, h0, l0);
                    split_bf16(e1, h1, l1);
                    const uint32_t off = (uint32_t)(row * 128 + (col & 63) * 2);
                    const uint32_t sw = off ^ (uint32_t)((row & 7) << 4);
                    uint32_t ph, pl;
                    {
                        __nv_bfloat162 tmp; tmp.x = h0; tmp.y = h1;
                        ph = *(uint32_t*)&tmp;
                        tmp.x = l0; tmp.y = l1;
                        pl = *(uint32_t*)&tmp;
                    }
                    *(uint32_t*)(Kc + (0 * 2 + wn) * 16384 + sw) = ph;
                    *(uint32_t*)(Kc + (1 * 2 + wn) * 16384 + sw) = pl;
                }
            }
        CP_WAIT(0);             // V_it complete
        __syncthreads();        // P visible to all; V visible to all

        do_mma(Kb, Vb, accO);   // out += P V^T
        __syncthreads();        // all warps done reading P/V

        if (it + 1 < NKEYS / 128) {
            load_region(Kb, Khp, Klp, Dd, bn + 128, 0);   // K_{it+1} into K/P region
            CP_COMMIT();
        }
    }

    // final: reduce row sums across quads and the two n-warps; scale + store
#pragma unroll
    for (int s = 0; s < 4; s++) {
        rs[s] += __shfl_xor_sync(0xffffffffu, rs[s], 1);
        rs[s] += __shfl_xor_sync(0xffffffffu, rs[s], 2);
    }
    if ((l & 3) == 0) {
#pragma unroll
        for (int s = 0; s < 4; s++) {
            const int row = wm * 32 + (s >> 1) * 16 + (l >> 2) + (s & 1) * 8;
            rbuf[wn * 128 + row] = rs[s];
        }
    }
    __syncthreads();

#pragma unroll
    for (int t = 0; t < 2; t++)
#pragma unroll
        for (int rh = 0; rh < 2; rh++) {
            const int row = wm * 32 + t * 16 + (l >> 2) + rh * 8;
            const float inv = 1.0f / (rbuf[row] + rbuf[128 + row]);
            float* orow = outp + (size_t)(bm + row) * Nn + (size_t)z * Dd;
#pragma unroll
            for (int nb = 0; nb < 8; nb++) {
                const int col = wn * 64 + nb * 8 + (l & 3) * 2;
                float2 v;
                v.x = accO[t][nb][rh * 2 + 0] * inv;
                v.y = accO[t][nb][rh * 2 + 1] * inv;
                *(float2*)(orow + col) = v;
            }
        }
}

// ---------------- prep kernels ----------------
__global__ __launch_bounds__(256) void convert_X(const float* __restrict__ X) {
    const size_t n = (size_t)Mq * Nn;
    for (size_t i = (size_t)blockIdx.x * blockDim.x + threadIdx.x; i < n;
         i += (size_t)gridDim.x * blockDim.x) {
        bf16 h, lo;
        split_bf16(X[i], h, lo);
        g_Xh[i] = h;
        g_Xl[i] = lo;
    }
}

__global__ __launch_bounds__(256) void transpose_convert_W(
    const float* __restrict__ W, bf16* __restrict__ oh, bf16* __restrict__ ol)
{
    __shared__ float t[32][33];
    const int n0 = blockIdx.x * 32, k0 = blockIdx.y * 32;
    const int tx = threadIdx.x, ty = threadIdx.y;
#pragma unroll
    for (int j = 0; j < 4; j++)
        t[ty + 8 * j][tx] = W[(size_t)(k0 + ty + 8 * j) * Nn + n0 + tx];
    __syncthreads();
#pragma unroll
    for (int j = 0; j < 4; j++) {
        const float v = t[tx][ty + 8 * j];
        const size_t o = (size_t)(n0 + ty + 8 * j) * Nn + k0 + tx;
        bf16 h, lo;
        split_bf16(v, h, lo);
        oh[o] = h;
        ol[o] = lo;
    }
}

__global__ __launch_bounds__(256) void convert_cacheK(const float* __restrict__ cK) {
    const size_t n = (size_t)Hh * Pp * Dd;
    for (size_t i = (size_t)blockIdx.x * blockDim.x + threadIdx.x; i < n;
         i += (size_t)gridDim.x * blockDim.x) {
        const size_t h = i / ((size_t)Pp * Dd);
        const size_t rr = i % ((size_t)Pp * Dd);
        bf16 hh, lo;
        split_bf16(cK[i], hh, lo);
        const size_t o = h * (size_t)NKEYS * Dd + rr;
        g_Kh[o] = hh;
        g_Kl[o] = lo;
    }
}

__global__ __launch_bounds__(256) void transpose_convert_V(const float* __restrict__ cV) {
    __shared__ float t[32][33];
    const int h = blockIdx.z;
    const int p0 = blockIdx.x * 32, d0 = blockIdx.y * 32;
    const int tx = threadIdx.x, ty = threadIdx.y;
#pragma unroll
    for (int j = 0; j < 4; j++)
        t[ty + 8 * j][tx] = cV[((size_t)h * Pp + p0 + ty + 8 * j) * Dd + d0 + tx];
    __syncthreads();
#pragma unroll
    for (int j = 0; j < 4; j++) {
        const float v = t[tx][ty + 8 * j];
        const size_t o = ((size_t)h * Dd + d0 + ty + 8 * j) * NKEYS + p0 + tx;
        bf16 hh, lo;
        split_bf16(v, hh, lo);
        g_Vth[o] = hh;
        g_Vtl[o] = lo;
    }
}

// ---------------- host launcher ----------------
extern "C" void kernel_launch(void* const* d_in, const int* in_sizes, int n_in,
                              void* d_out, int out_size)
{
    const float* X  = (const float*)d_in[0];
    const float* Wq = (const float*)d_in[1];
    const float* Wk = (const float*)d_in[2];
    const float* Wv = (const float*)d_in[3];
    const float* cK = (const float*)d_in[4];
    const float* cV = (const float*)d_in[5];
    float* out = (float*)d_out;

    bf16 *xh, *xl, *wh, *wl;
    cudaGetSymbolAddress((void**)&xh, g_Xh);   cudaGetSymbolAddress((void**)&xl, g_Xl);
    cudaGetSymbolAddress((void**)&wh, g_Wh);   cudaGetSymbolAddress((void**)&wl, g_Wl);

    cudaFuncSetAttribute(proj_kernel<0>, cudaFuncAttributeMaxDynamicSharedMemorySize, SMEM_PROJ);
    cudaFuncSetAttribute(proj_kernel<1>, cudaFuncAttributeMaxDynamicSharedMemorySize, SMEM_PROJ);
    cudaFuncSetAttribute(proj_kernel<2>, cudaFuncAttributeMaxDynamicSharedMemorySize, SMEM_PROJ);
    cudaFuncSetAttribute(attn_kernel,    cudaFuncAttributeMaxDynamicSharedMemorySize, SMEM_ATT);

    // prep
    convert_X<<<2048, 256>>>(X);
    transpose_convert_W<<<dim3(128, 128), dim3(32, 8)>>>(Wq, wh + (size_t)0 * Nn * Nn, wl + (size_t)0 * Nn * Nn);
    transpose_convert_W<<<dim3(128, 128), dim3(32, 8)>>>(Wk, wh + (size_t)1 * Nn * Nn, wl + (size_t)1 * Nn * Nn);
    transpose_convert_W<<<dim3(128, 128), dim3(32, 8)>>>(Wv, wh + (size_t)2 * Nn * Nn, wl + (size_t)2 * Nn * Nn);
    convert_cacheK<<<8192, 256>>>(cK);
    transpose_convert_V<<<dim3(Pp / 32, Dd / 32, Hh), dim3(32, 8)>>>(cV);

    // projections
    {
        dim3 grid(Nn / 128, Mq / 128, 1);
        proj_kernel<0><<<grid, 256, SMEM_PROJ>>>(xh, xl, Nn,
            wh + (size_t)0 * Nn * Nn, wl + (size_t)0 * Nn * Nn, Nn, Nn);
        proj_kernel<1><<<grid, 256, SMEM_PROJ>>>(xh, xl, Nn,
            wh + (size_t)1 * Nn * Nn, wl + (size_t)1 * Nn * Nn, Nn, Nn);
        proj_kernel<2><<<grid, 256, SMEM_PROJ>>>(xh, xl, Nn,
            wh + (size_t)2 * Nn * Nn, wl + (size_t)2 * Nn * Nn, Nn, Nn);
    }

    // fused attention
    attn_kernel<<<dim3(Mq / 128, Hh), 256, SMEM_ATT>>>(out);
}

// round 6
// speedup vs baseline: 1.5541x; 1.5541x over previous
#include <cuda_runtime.h>
#include <cuda_bf16.h>
#include <math.h>
#include <stdint.h>

#define Mq 1024
#define Nn 4096
#define Dd 128
#define Pp 3072
#define Hh 32
#define NKEYS 4096
typedef __nv_bfloat16 bf16;

// ---------------- scratch ----------------
__device__ bf16 g_Xh[(size_t)Mq * Nn],       g_Xl[(size_t)Mq * Nn];
__device__ bf16 g_Wh[(size_t)3 * Nn * Nn],   g_Wl[(size_t)3 * Nn * Nn];      // natural [k][n]
__device__ bf16 g_Qh[(size_t)Hh * Mq * Dd],  g_Ql[(size_t)Hh * Mq * Dd];
__device__ bf16 g_Kh[(size_t)Hh * NKEYS * Dd], g_Kl[(size_t)Hh * NKEYS * Dd];
__device__ bf16 g_Vh[(size_t)Hh * NKEYS * Dd], g_Vl[(size_t)Hh * NKEYS * Dd]; // natural [key][d]

// ---------------- helpers ----------------
static __device__ __forceinline__ uint32_t smem_u32(const void* p) {
    uint32_t a;
    asm("{ .reg .u64 t; cvta.to.shared.u64 t, %1; cvt.u32.u64 %0, t; }" : "=r"(a) : "l"(p));
    return a;
}
static __device__ __forceinline__ void cp_async16(uint32_t dst, const void* src) {
    asm volatile("cp.async.cg.shared.global [%0], [%1], 16;" :: "r"(dst), "l"(src));
}
#define CP_COMMIT() asm volatile("cp.async.commit_group;" ::: "memory")
#define CP_WAIT(n)  asm volatile("cp.async.wait_group %0;" :: "n"(n) : "memory")

static __device__ __forceinline__ void ldsm_x4(uint32_t& r0, uint32_t& r1, uint32_t& r2, uint32_t& r3,
                                               uint32_t addr) {
    asm volatile("ldmatrix.sync.aligned.m8n8.x4.shared.b16 {%0,%1,%2,%3}, [%4];"
                 : "=r"(r0), "=r"(r1), "=r"(r2), "=r"(r3) : "r"(addr));
}
static __device__ __forceinline__ void ldsm_x4_t(uint32_t& r0, uint32_t& r1, uint32_t& r2, uint32_t& r3,
                                                 uint32_t addr) {
    asm volatile("ldmatrix.sync.aligned.m8n8.x4.trans.shared.b16 {%0,%1,%2,%3}, [%4];"
                 : "=r"(r0), "=r"(r1), "=r"(r2), "=r"(r3) : "r"(addr));
}
static __device__ __forceinline__ void mma_bf16(float* c, const uint32_t* a, const uint32_t* b) {
    asm volatile(
        "mma.sync.aligned.m16n8k16.row.col.f32.bf16.bf16.f32 "
        "{%0,%1,%2,%3}, {%4,%5,%6,%7}, {%8,%9}, {%0,%1,%2,%3};"
        : "+f"(c[0]), "+f"(c[1]), "+f"(c[2]), "+f"(c[3])
        : "r"(a[0]), "r"(a[1]), "r"(a[2]), "r"(a[3]), "r"(b[0]), "r"(b[1]));
}
static __device__ __forceinline__ void split_bf16(float v, bf16& h, bf16& l) {
    h = __float2bfloat16(v);
    l = __float2bfloat16(v - __bfloat162float(h));
}

#define SMEM_PROJ (1024 + 2 * 4 * 16384)
#define SMEM_ATT  (1024 + 3 * 4 * 16384)

// ---------------- fused projection GEMM (z = 0:Q, 1:K, 2:V) ----------------
// A = X [m][k] split planes; B = W natural [k][n], fragments via ldsm.trans.
__global__ __launch_bounds__(256, 1) void proj_kernel(
    const bf16* __restrict__ Xh, const bf16* __restrict__ Xl,
    const bf16* __restrict__ Wh, const bf16* __restrict__ Wl)
{
    extern __shared__ char smem[];
    float* rbuf = (float*)smem;
    const uint32_t sb = smem_u32(smem);
    const int tid = threadIdx.x;
    const int wid = tid >> 5, l = tid & 31;
    const int wm = wid >> 1, wn = wid & 1;
    const int bn = blockIdx.x * 128, bm = blockIdx.y * 128, z = blockIdx.z;

    const bf16* WhP = Wh + (size_t)z * Nn * Nn;
    const bf16* WlP = Wl + (size_t)z * Nn * Nn;

    float acc[2][8][4];
#pragma unroll
    for (int t = 0; t < 2; t++)
#pragma unroll
        for (int nb = 0; nb < 8; nb++)
#pragma unroll
            for (int i = 0; i < 4; i++) acc[t][nb][i] = 0.f;

    auto load_chunk = [&](int c) {
        const int st = c & 1;
        const int k0 = c << 6;
        const uint32_t stb = sb + 1024 + st * 65536;
        // A planes 0(hi),1(lo): [128 m][128B]
#pragma unroll
        for (int p = 0; p < 2; p++) {
            const bf16* src = p ? Xl : Xh;
#pragma unroll
            for (int i = tid; i < 1024; i += 256) {
                const int row = i >> 3, cc = i & 7;
                const uint32_t off = (uint32_t)(row * 128 + cc * 16);
                cp_async16(stb + p * 16384 + (off ^ (uint32_t)((row & 7) << 4)),
                           src + (size_t)(bm + row) * Nn + k0 + cc * 8);
            }
        }
        // B planes 2(hi),3(lo): [64 k][256B] natural W rows
#pragma unroll
        for (int p = 0; p < 2; p++) {
            const bf16* src = p ? WlP : WhP;
#pragma unroll
            for (int i = tid; i < 1024; i += 256) {
                const int row = i >> 4, c16 = i & 15;
                const uint32_t off = (uint32_t)(row * 256 + c16 * 16);
                cp_async16(stb + (2 + p) * 16384 + (off ^ (uint32_t)((row & 7) << 4)),
                           src + (size_t)(k0 + row) * Nn + bn + c16 * 8);
            }
        }
        CP_COMMIT();
    };

    const int nch = Nn >> 6;
    load_chunk(0);
    load_chunk(1);

    for (int c = 0; c < nch; c++) {
        if (c + 1 < nch) { CP_WAIT(1); } else { CP_WAIT(0); }
        __syncthreads();
        const uint32_t sbase = sb + 1024 + (c & 1) * 65536;

#pragma unroll
        for (int kk = 0; kk < 4; kk++) {
            uint32_t aH[2][4], aL[2][4];
#pragma unroll
            for (int t = 0; t < 2; t++) {
                const int mrow = wm * 32 + t * 16 + (l & 7) + ((l >> 3) & 1) * 8;
                const int kb = kk * 32 + ((l >> 4) & 1) * 16;
                const uint32_t ao = (uint32_t)(mrow * 128) + (uint32_t)(kb ^ ((mrow & 7) << 4));
                ldsm_x4(aH[t][0], aH[t][1], aH[t][2], aH[t][3], sbase + 0 * 16384 + ao);
                ldsm_x4(aL[t][0], aL[t][1], aL[t][2], aL[t][3], sbase + 1 * 16384 + ao);
            }
            uint32_t bH[8][2], bL[8][2];
#pragma unroll
            for (int bt = 0; bt < 4; bt++) {
                const int krow = kk * 16 + (l & 7) + ((l >> 3) & 1) * 8;
                const int colb = wn * 128 + bt * 32 + ((l >> 4) & 1) * 16;
                const uint32_t bo = (uint32_t)(krow * 256) + (uint32_t)(colb ^ ((krow & 7) << 4));
                ldsm_x4_t(bH[2 * bt][0], bH[2 * bt][1], bH[2 * bt + 1][0], bH[2 * bt + 1][1],
                          sbase + 2 * 16384 + bo);
                ldsm_x4_t(bL[2 * bt][0], bL[2 * bt][1], bL[2 * bt + 1][0], bL[2 * bt + 1][1],
                          sbase + 3 * 16384 + bo);
            }
#pragma unroll
            for (int t = 0; t < 2; t++)
#pragma unroll
                for (int nb = 0; nb < 8; nb++) {
                    mma_bf16(acc[t][nb], aH[t], bH[nb]);
                    mma_bf16(acc[t][nb], aH[t], bL[nb]);
                    mma_bf16(acc[t][nb], aL[t], bH[nb]);
                }
        }
        __syncthreads();
        if (c + 2 < nch) load_chunk(c + 2);
    }

    // acc[t][nb][i] -> row = wm*32+t*16+(l>>2)+(i>>1)*8, col = wn*64+nb*8+(l&3)*2+(i&1)
    float scale_num = 1.0f;
    if (z < 2) {
        float ss[4] = {0.f, 0.f, 0.f, 0.f};
#pragma unroll
        for (int t = 0; t < 2; t++)
#pragma unroll
            for (int nb = 0; nb < 8; nb++)
#pragma unroll
                for (int i = 0; i < 4; i++) {
                    const float v = acc[t][nb][i];
                    ss[t * 2 + (i >> 1)] += v * v;
                }
#pragma unroll
        for (int s = 0; s < 4; s++) {
            ss[s] += __shfl_xor_sync(0xffffffffu, ss[s], 1);
            ss[s] += __shfl_xor_sync(0xffffffffu, ss[s], 2);
        }
        if ((l & 3) == 0) {
#pragma unroll
            for (int s = 0; s < 4; s++) {
                const int row = wm * 32 + (s >> 1) * 16 + (l >> 2) + (s & 1) * 8;
                rbuf[wn * 128 + row] = ss[s];
            }
        }
        __syncthreads();
    }
    (void)scale_num;

    bf16* dh = (z == 0) ? g_Qh : (z == 1) ? g_Kh : g_Vh;
    bf16* dl = (z == 0) ? g_Ql : (z == 1) ? g_Kl : g_Vl;
#pragma unroll
    for (int t = 0; t < 2; t++)
#pragma unroll
        for (int rh = 0; rh < 2; rh++) {
            const int row = wm * 32 + t * 16 + (l >> 2) + rh * 8;
            float sc = 1.0f;
            if (z < 2) sc = rsqrtf((rbuf[row] + rbuf[128 + row]) * (1.0f / 128.0f));
            const size_t rowbase = (z == 0)
                ? ((size_t)blockIdx.x * Mq + bm + row) * 128
                : ((size_t)blockIdx.x * NKEYS + Pp + bm + row) * 128;
#pragma unroll
            for (int nb = 0; nb < 8; nb++) {
                const int col = wn * 64 + nb * 8 + (l & 3) * 2;
                const float v0 = acc[t][nb][rh * 2 + 0] * sc;
                const float v1 = acc[t][nb][rh * 2 + 1] * sc;
                bf16 h0, l0, h1, l1;
                split_bf16(v0, h0, l0);
                split_bf16(v1, h1, l1);
                __nv_bfloat162 ph; ph.x = h0; ph.y = h1;
                __nv_bfloat162 pl; pl.x = l0; pl.y = l1;
                *(__nv_bfloat162*)(dh + rowbase + col) = ph;
                *(__nv_bfloat162*)(dl + rowbase + col) = pl;
            }
        }
}

// ---------------- fused flash attention ----------------
__global__ __launch_bounds__(256, 1) void attn_kernel(float* __restrict__ outp)
{
    extern __shared__ char smem[];
    float* rbuf = (float*)smem;
    const uint32_t sb = smem_u32(smem);
    const uint32_t Qb = sb + 1024;
    const uint32_t Kb = Qb + 65536;
    const uint32_t Vb = Kb + 65536;
    char* Kc = smem + 1024 + 65536;

    const int tid = threadIdx.x;
    const int wid = tid >> 5, l = tid & 31;
    const int wm = wid >> 1, wn = wid & 1;
    const int bm = blockIdx.x * 128;
    const int z = blockIdx.y;

    const bf16* Qhp = g_Qh + ((size_t)z * Mq + bm) * Dd;
    const bf16* Qlp = g_Ql + ((size_t)z * Mq + bm) * Dd;
    const bf16* Khp = g_Kh + (size_t)z * NKEYS * Dd;
    const bf16* Klp = g_Kl + (size_t)z * NKEYS * Dd;
    const bf16* Vhp = g_Vh + (size_t)z * NKEYS * Dd;
    const bf16* Vlp = g_Vl + (size_t)z * NKEYS * Dd;

    // Q/K regions: 4 planes [128 rows][128B]: p = split*2 + k-chunk
    auto load_region = [&](uint32_t dstb, const bf16* srcH, const bf16* srcL, int row0) {
#pragma unroll
        for (int p = 0; p < 4; p++) {
            const bf16* src = (p < 2) ? srcH : srcL;
            const int k0 = (p & 1) * 64;
#pragma unroll
            for (int i = tid; i < 1024; i += 256) {
                const int row = i >> 3, cc = i & 7;
                const uint32_t off = (uint32_t)(row * 128 + cc * 16);
                cp_async16(dstb + p * 16384 + (off ^ (uint32_t)((row & 7) << 4)),
                           src + (size_t)(row0 + row) * Dd + k0 + cc * 8);
            }
        }
    };
    // V region: 2 planes [128 key][256B] natural layout
    auto load_v = [&](int bn) {
#pragma unroll
        for (int p = 0; p < 2; p++) {
            const bf16* src = p ? Vlp : Vhp;
#pragma unroll
            for (int i = tid; i < 2048; i += 256) {
                const int row = i >> 4, c16 = i & 15;
                const uint32_t off = (uint32_t)(row * 256 + c16 * 16);
                cp_async16(Vb + p * 32768 + (off ^ (uint32_t)((row & 7) << 4)),
                           src + (size_t)(bn + row) * Dd + c16 * 8);
            }
        }
    };

    // QK: both operands in [row][128B]-plane regions
    auto do_mma_qk = [&](float acc[2][8][4]) {
#pragma unroll
        for (int c = 0; c < 2; c++) {
            const uint32_t aHb = Qb + c * 16384, aLb = Qb + (2 + c) * 16384;
            const uint32_t bHb = Kb + c * 16384, bLb = Kb + (2 + c) * 16384;
#pragma unroll
            for (int kk = 0; kk < 4; kk++) {
                uint32_t aH[2][4], aL[2][4];
#pragma unroll
                for (int t = 0; t < 2; t++) {
                    const int mrow = wm * 32 + t * 16 + (l & 7) + ((l >> 3) & 1) * 8;
                    const int kb = kk * 32 + ((l >> 4) & 1) * 16;
                    const uint32_t ao = (uint32_t)(mrow * 128) + (uint32_t)(kb ^ ((mrow & 7) << 4));
                    ldsm_x4(aH[t][0], aH[t][1], aH[t][2], aH[t][3], aHb + ao);
                    ldsm_x4(aL[t][0], aL[t][1], aL[t][2], aL[t][3], aLb + ao);
                }
                uint32_t bH[8][2], bL[8][2];
#pragma unroll
                for (int bt = 0; bt < 4; bt++) {
                    const int nrow = wn * 64 + bt * 16 + (l & 7) + ((l >> 4) & 1) * 8;
                    const int kb = kk * 32 + ((l >> 3) & 1) * 16;
                    const uint32_t bo = (uint32_t)(nrow * 128) + (uint32_t)(kb ^ ((nrow & 7) << 4));
                    ldsm_x4(bH[2 * bt][0], bH[2 * bt][1], bH[2 * bt + 1][0], bH[2 * bt + 1][1], bHb + bo);
                    ldsm_x4(bL[2 * bt][0], bL[2 * bt][1], bL[2 * bt + 1][0], bL[2 * bt + 1][1], bLb + bo);
                }
#pragma unroll
                for (int t = 0; t < 2; t++)
#pragma unroll
                    for (int nb = 0; nb < 8; nb++) {
                        mma_bf16(acc[t][nb], aH[t], bH[nb]);
                        mma_bf16(acc[t][nb], aH[t], bL[nb]);
                        mma_bf16(acc[t][nb], aL[t], bH[nb]);
                    }
            }
        }
    };

    // PV: A = P (in K region planes), B = V via ldsm.trans from natural layout
    auto do_mma_pv = [&](float acc[2][8][4]) {
#pragma unroll
        for (int c = 0; c < 2; c++) {
            const uint32_t aHb = Kb + c * 16384, aLb = Kb + (2 + c) * 16384;
#pragma unroll
            for (int kk = 0; kk < 4; kk++) {
                uint32_t aH[2][4], aL[2][4];
#pragma unroll
                for (int t = 0; t < 2; t++) {
                    const int mrow = wm * 32 + t * 16 + (l & 7) + ((l >> 3) & 1) * 8;
                    const int kb = kk * 32 + ((l >> 4) & 1) * 16;
                    const uint32_t ao = (uint32_t)(mrow * 128) + (uint32_t)(kb ^ ((mrow & 7) << 4));
                    ldsm_x4(aH[t][0], aH[t][1], aH[t][2], aH[t][3], aHb + ao);
                    ldsm_x4(aL[t][0], aL[t][1], aL[t][2], aL[t][3], aLb + ao);
                }
                uint32_t bH[8][2], bL[8][2];
#pragma unroll
                for (int bt = 0; bt < 4; bt++) {
                    const int key = c * 64 + kk * 16 + (l & 7) + ((l >> 3) & 1) * 8;
                    const int colb = wn * 128 + bt * 32 + ((l >> 4) & 1) * 16;
                    const uint32_t bo = (uint32_t)(key * 256) + (uint32_t)(colb ^ ((key & 7) << 4));
                    ldsm_x4_t(bH[2 * bt][0], bH[2 * bt][1], bH[2 * bt + 1][0], bH[2 * bt + 1][1],
                              Vb + 0 * 32768 + bo);
                    ldsm_x4_t(bL[2 * bt][0], bL[2 * bt][1], bL[2 * bt + 1][0], bL[2 * bt + 1][1],
                              Vb + 1 * 32768 + bo);
                }
#pragma unroll
                for (int t = 0; t < 2; t++)
#pragma unroll
                    for (int nb = 0; nb < 8; nb++) {
                        mma_bf16(acc[t][nb], aH[t], bH[nb]);
                        mma_bf16(acc[t][nb], aH[t], bL[nb]);
                        mma_bf16(acc[t][nb], aL[t], bH[nb]);
                    }
            }
        }
    };

    float accO[2][8][4];
#pragma unroll
    for (int t = 0; t < 2; t++)
#pragma unroll
        for (int nb = 0; nb < 8; nb++)
#pragma unroll
            for (int i = 0; i < 4; i++) accO[t][nb][i] = 0.f;
    float rs[4] = {0.f, 0.f, 0.f, 0.f};

    load_region(Qb, Qhp, Qlp, 0);
    load_region(Kb, Khp, Klp, 0);
    CP_COMMIT();

    for (int it = 0; it < NKEYS / 128; it++) {
        const int bn = it * 128;
        load_v(bn);
        CP_COMMIT();

        CP_WAIT(1);
        __syncthreads();

        float accS[2][8][4];
#pragma unroll
        for (int t = 0; t < 2; t++)
#pragma unroll
            for (int nb = 0; nb < 8; nb++)
#pragma unroll
                for (int i = 0; i < 4; i++) accS[t][nb][i] = 0.f;

        do_mma_qk(accS);
        __syncthreads();

#pragma unroll
        for (int t = 0; t < 2; t++)
#pragma unroll
            for (int rh = 0; rh < 2; rh++) {
                const int row = wm * 32 + t * 16 + (l >> 2) + rh * 8;
#pragma unroll
                for (int nb = 0; nb < 8; nb++) {
                    const int col = wn * 64 + nb * 8 + (l & 3) * 2;
                    const float e0 = __expf(accS[t][nb][rh * 2 + 0]);
                    const float e1 = __expf(accS[t][nb][rh * 2 + 1]);
                    rs[t * 2 + rh] += e0 + e1;
                    bf16 h0, l0, h1, l1;
                    split_bf16(e0, h0, l0);
                    split_bf16(e1, h1, l1);
                    const uint32_t off = (uint32_t)(row * 128 + (col & 63) * 2);
                    const uint32_t sw = off ^ (uint32_t)((row & 7) << 4);
                    uint32_t ph, pl;
                    {
                        __nv_bfloat162 tmp; tmp.x = h0; tmp.y = h1;
                        ph = *(uint32_t*)&tmp;
                        tmp.x = l0; tmp.y = l1;
                        pl = *(uint32_t*)&tmp;
                    }
                    *(uint32_t*)(Kc + (0 * 2 + wn) * 16384 + sw) = ph;
                    *(uint32_t*)(Kc + (1 * 2 + wn) * 16384 + sw) = pl;
                }
            }
        CP_WAIT(0);
        __syncthreads();

        do_mma_pv(accO);
        __syncthreads();

        if (it + 1 < NKEYS / 128) {
            load_region(Kb, Khp, Klp, bn + 128);
            CP_COMMIT();
        }
    }

#pragma unroll
    for (int s = 0; s < 4; s++) {
        rs[s] += __shfl_xor_sync(0xffffffffu, rs[s], 1);
        rs[s] += __shfl_xor_sync(0xffffffffu, rs[s], 2);
    }
    if ((l & 3) == 0) {
#pragma unroll
        for (int s = 0; s < 4; s++) {
            const int row = wm * 32 + (s >> 1) * 16 + (l >> 2) + (s & 1) * 8;
            rbuf[wn * 128 + row] = rs[s];
        }
    }
    __syncthreads();

#pragma unroll
    for (int t = 0; t < 2; t++)
#pragma unroll
        for (int rh = 0; rh < 2; rh++) {
            const int row = wm * 32 + t * 16 + (l >> 2) + rh * 8;
            const float inv = 1.0f / (rbuf[row] + rbuf[128 + row]);
            float* orow = outp + (size_t)(bm + row) * Nn + (size_t)z * Dd;
#pragma unroll
            for (int nb = 0; nb < 8; nb++) {
                const int col = wn * 64 + nb * 8 + (l & 3) * 2;
                float2 v;
                v.x = accO[t][nb][rh * 2 + 0] * inv;
                v.y = accO[t][nb][rh * 2 + 1] * inv;
                *(float2*)(orow + col) = v;
            }
        }
}

// ---------------- prep kernels (all contiguous) ----------------
__global__ __launch_bounds__(256) void convert_inputs(
    const float* __restrict__ X, const float* __restrict__ cK, const float* __restrict__ cV)
{
    const size_t stride = (size_t)gridDim.x * blockDim.x;
    const size_t tid0 = (size_t)blockIdx.x * blockDim.x + threadIdx.x;

    for (size_t i = tid0; i < (size_t)Mq * Nn; i += stride) {
        bf16 h, lo;
        split_bf16(X[i], h, lo);
        g_Xh[i] = h; g_Xl[i] = lo;
    }
    const size_t nkv = (size_t)Hh * Pp * Dd;
    for (size_t i = tid0; i < nkv; i += stride) {
        const size_t h = i / ((size_t)Pp * Dd);
        const size_t r = i % ((size_t)Pp * Dd);
        const size_t o = h * (size_t)NKEYS * Dd + r;
        bf16 hh, lo;
        split_bf16(cK[i], hh, lo);
        g_Kh[o] = hh; g_Kl[o] = lo;
        split_bf16(cV[i], hh, lo);
        g_Vh[o] = hh; g_Vl[o] = lo;
    }
}

__global__ __launch_bounds__(256) void convert_W(
    const float* __restrict__ Wq, const float* __restrict__ Wk, const float* __restrict__ Wv)
{
    const int z = blockIdx.y;
    const float* W = (z == 0) ? Wq : (z == 1) ? Wk : Wv;
    bf16* oh = g_Wh + (size_t)z * Nn * Nn;
    bf16* ol = g_Wl + (size_t)z * Nn * Nn;
    const size_t n = (size_t)Nn * Nn;
    for (size_t i = (size_t)blockIdx.x * blockDim.x + threadIdx.x; i < n;
         i += (size_t)gridDim.x * blockDim.x) {
        bf16 h, lo;
        split_bf16(W[i], h, lo);
        oh[i] = h; ol[i] = lo;
    }
}

// ---------------- host launcher ----------------
extern "C" void kernel_launch(void* const* d_in, const int* in_sizes, int n_in,
                              void* d_out, int out_size)
{
    const float* X  = (const float*)d_in[0];
    const float* Wq = (const float*)d_in[1];
    const float* Wk = (const float*)d_in[2];
    const float* Wv = (const float*)d_in[3];
    const float* cK = (const float*)d_in[4];
    const float* cV = (const float*)d_in[5];
    float* out = (float*)d_out;

    bf16 *xh, *xl, *wh, *wl;
    cudaGetSymbolAddress((void**)&xh, g_Xh);
    cudaGetSymbolAddress((void**)&xl, g_Xl);
    cudaGetSymbolAddress((void**)&wh, g_Wh);
    cudaGetSymbolAddress((void**)&wl, g_Wl);

    cudaFuncSetAttribute(proj_kernel, cudaFuncAttributeMaxDynamicSharedMemorySize, SMEM_PROJ);
    cudaFuncSetAttribute(attn_kernel, cudaFuncAttributeMaxDynamicSharedMemorySize, SMEM_ATT);

    convert_inputs<<<4096, 256>>>(X, cK, cV);
    convert_W<<<dim3(4096, 3), 256>>>(Wq, Wk, Wv);

    proj_kernel<<<dim3(Nn / 128, Mq / 128, 3), 256, SMEM_PROJ>>>(xh, xl, wh, wl);

    attn_kernel<<<dim3(Mq / 128, Hh), 256, SMEM_ATT>>>(out);
}